// round 2
// baseline (speedup 1.0000x reference)
#include <cuda_runtime.h>
#include <math.h>

// Problem constants (fixed by setup_inputs)
#define XY 10
#define Zdim 5
#define S 500
#define NT 10000
#define Bsz 32
#define Tlen 40
#define Llen 20
#define NEGV (-1e9f)

// ---------------------------------------------------------------------------
// Kernel 1: emission sums, transpose-free.
// Each block owns 2 states (2 rows of logE, 80 KB in shared, interleaved
// [token][2]); threads loop over all (b,t) sentences gathering float2 per
// token. logE is read exactly once from DRAM, fully coalesced.
// ---------------------------------------------------------------------------
__global__ void __launch_bounds__(512, 2) em_kernel(
    const float* __restrict__ logE,
    const int* __restrict__ stories,
    float* __restrict__ out)
{
    extern __shared__ float sh[];          // [NT][2] interleaved = 80000 B
    const int s0 = blockIdx.x * 2;

    // Load 2 rows, coalesced float4, scatter into interleaved layout
    const float4* r0 = (const float4*)(logE + (long)s0 * NT);
    const float4* r1 = (const float4*)(logE + (long)(s0 + 1) * NT);
    for (int i = threadIdx.x; i < NT / 4; i += blockDim.x) {
        float4 a = __ldg(&r0[i]);
        float4 b = __ldg(&r1[i]);
        int t4 = i * 4;
        sh[(t4 + 0) * 2 + 0] = a.x; sh[(t4 + 0) * 2 + 1] = b.x;
        sh[(t4 + 1) * 2 + 0] = a.y; sh[(t4 + 1) * 2 + 1] = b.y;
        sh[(t4 + 2) * 2 + 0] = a.z; sh[(t4 + 2) * 2 + 1] = b.z;
        sh[(t4 + 3) * 2 + 0] = a.w; sh[(t4 + 3) * 2 + 1] = b.w;
    }
    __syncthreads();

    const float2* sh2 = (const float2*)sh;
    for (int bt = threadIdx.x; bt < Bsz * Tlen; bt += blockDim.x) {
        const int4* tp = (const int4*)(stories + bt * Llen);
        int4 q0 = __ldg(&tp[0]);
        int4 q1 = __ldg(&tp[1]);
        int4 q2 = __ldg(&tp[2]);
        int4 q3 = __ldg(&tp[3]);
        int4 q4 = __ldg(&tp[4]);
        float ax = 0.f, ay = 0.f;
#define GATH(tk) { float2 v = sh2[tk]; ax += v.x; ay += v.y; }
        GATH(q0.x) GATH(q0.y) GATH(q0.z) GATH(q0.w)
        GATH(q1.x) GATH(q1.y) GATH(q1.z) GATH(q1.w)
        GATH(q2.x) GATH(q2.y) GATH(q2.z) GATH(q2.w)
        GATH(q3.x) GATH(q3.y) GATH(q3.z) GATH(q3.w)
        GATH(q4.x) GATH(q4.y) GATH(q4.z) GATH(q4.w)
#undef GATH
        int b = bt / Tlen;
        int t = bt % Tlen;
        float2* op = (float2*)(out + ((long)t * Bsz + b) * S + s0);
        *op = make_float2(ax, ay);
    }
}

// ---------------------------------------------------------------------------
// Kernel 2: forward recursion. One block per story; alpha double-buffered
// in shared; 7-sparse transition stencil in registers.
// ---------------------------------------------------------------------------
__global__ void __launch_bounds__(512, 1) forward_kernel(
    const float* __restrict__ prior,
    const float* __restrict__ logT,
    float* __restrict__ out)
{
    __shared__ float buf[2][512];
    const int s = threadIdx.x;
    const int b = blockIdx.x;
    const bool act = (s < S);

    float w[7];
    int   nb[7];
    if (act) {
        int z = s / (XY * XY);
        int r = s % (XY * XY);
        int y = r / XY;
        int x = r % XY;
        const float* row = logT + (long)s * S;
        bool v1 = (x + 1 < XY), v2 = (x - 1 >= 0);
        bool v3 = (y + 1 < XY), v4 = (y - 1 >= 0);
        bool v5 = (z + 1 < Zdim), v6 = (z + 2 < Zdim);
        nb[0] = s;                     w[0] = __ldg(&row[s]);
        nb[1] = v1 ? s + 1   : s;      w[1] = v1 ? __ldg(&row[s + 1])   : NEGV;
        nb[2] = v2 ? s - 1   : s;      w[2] = v2 ? __ldg(&row[s - 1])   : NEGV;
        nb[3] = v3 ? s + XY  : s;      w[3] = v3 ? __ldg(&row[s + XY])  : NEGV;
        nb[4] = v4 ? s - XY  : s;      w[4] = v4 ? __ldg(&row[s - XY])  : NEGV;
        nb[5] = v5 ? s + XY*XY   : s;  w[5] = v5 ? __ldg(&row[s + XY*XY])   : NEGV;
        nb[6] = v6 ? s + 2*XY*XY : s;  w[6] = v6 ? __ldg(&row[s + 2*XY*XY]) : NEGV;
    }

    // t = 0: alpha0 = em0 + prior (em already in out)
    if (act) {
        float a0 = out[(0 * Bsz + b) * S + s] + __ldg(&prior[s]);
        out[(0 * Bsz + b) * S + s] = a0;
        buf[0][s] = a0;
    }
    __syncthreads();

    float em_next = 0.0f;
    if (act) em_next = out[(1 * Bsz + b) * S + s];

    int cur = 0;
    for (int t = 1; t < Tlen; t++) {
        float em_t = em_next;
        if (act && t + 1 < Tlen) em_next = out[((t + 1) * Bsz + b) * S + s];

        if (act) {
            float v[7];
            float m = NEGV;
#pragma unroll
            for (int k = 0; k < 7; k++) {
                v[k] = w[k] + buf[cur][nb[k]];
                m = fmaxf(m, v[k]);
            }
            float sum = 0.0f;
#pragma unroll
            for (int k = 0; k < 7; k++)
                sum += __expf(v[k] - m);
            float a = em_t + m + __logf(sum);
            buf[cur ^ 1][s] = a;
            out[((long)t * Bsz + b) * S + s] = a;
        }
        __syncthreads();
        cur ^= 1;
    }
}

// ---------------------------------------------------------------------------
extern "C" void kernel_launch(void* const* d_in, const int* in_sizes, int n_in,
                              void* d_out, int out_size) {
    const float* log_priors      = (const float*)d_in[0];
    const float* log_transitions = (const float*)d_in[1];
    const float* log_emissions   = (const float*)d_in[2];
    const int*   stories         = (const int*)d_in[3];
    float* out = (float*)d_out;

    static bool attr_set = false;
    if (!attr_set) {
        cudaFuncSetAttribute(em_kernel,
                             cudaFuncAttributeMaxDynamicSharedMemorySize,
                             NT * 2 * (int)sizeof(float));
        attr_set = true;
    }

    // 1) emission sums straight into d_out (no transpose)
    em_kernel<<<S / 2, 512, NT * 2 * sizeof(float)>>>(log_emissions, stories, out);

    // 2) forward recursion (in-place on d_out)
    forward_kernel<<<Bsz, 512>>>(log_priors, log_transitions, out);
}